// round 14
// baseline (speedup 1.0000x reference)
#include <cuda_runtime.h>

// SuperLoss mean, single-kernel. loss_i = (l-tau)*sigma + 0.25*ln(sigma)^2,
// sigma = exp(-W0(y)), y = max(-1/e, 2*(l-tau)).
//
// w = -1 + p*g(p), p = sqrt(max(2e*t2 + 2, 0)), t2 = 2*(l-tau).
// Degree-5 poly for g pre-scaled by -log2e: z = -w*log2e feeds ex2.approx;
// 0.25*w^2 = K*z^2 folded into the final combine. Arithmetic identical to
// R9-R12 (rel_err 2.7e-7) — frozen.
//
// R13: memory-axis experiment. MLP=8 (8 batched 16B loads/iter, exactly 4
// iterations/thread at N=2^25 with 1024x256 grid, no tail), default cache
// policy (drop .cs), launch_bounds(256,4). Occupancy proven non-binding in
// R10/R11; spending registers on MLP instead.

#define NEG_2TAU  (-11.5981853089210513f)
#define TWO_E     ( 5.43656365691809047f)
#define LOG2E_F   ( 1.44269504088896341f)

#define D5 ( 4.8619e-4f)
#define D4 (-7.70688e-3f)
#define D3 ( 4.942817e-2f)
#define D2 (-1.7750919e-1f)
#define D1 ( 4.7082352e-1f)
#define D0 (-1.44269504f)

#define NBLOCKS  1024
#define NTHREADS 256

typedef unsigned long long u64;

__device__ float g_partA[NBLOCKS];
__device__ float g_partB[NBLOCKS];
__device__ unsigned int g_cnt = 0;   // self-resets via atomicInc wraparound

__device__ __forceinline__ u64 pk2(float lo, float hi) {
    u64 r; asm("mov.b64 %0, {%1, %2};" : "=l"(r) : "f"(lo), "f"(hi)); return r;
}
__device__ __forceinline__ void upk2(float& lo, float& hi, u64 v) {
    asm("mov.b64 {%0, %1}, %2;" : "=f"(lo), "=f"(hi) : "l"(v));
}
__device__ __forceinline__ u64 fma2(u64 a, u64 b, u64 c) {
    u64 d; asm("fma.rn.f32x2 %0, %1, %2, %3;" : "=l"(d) : "l"(a), "l"(b), "l"(c)); return d;
}
__device__ __forceinline__ float fsqrt(float x) {
    float r; asm("sqrt.approx.f32 %0, %1;" : "=f"(r) : "f"(x)); return r;
}
__device__ __forceinline__ float fex2(float x) {
    float r; asm("ex2.approx.f32 %0, %1;" : "=f"(r) : "f"(x)); return r;
}

struct PkConsts {
    u64 cTwo, cN2T, c2E, cD5, cD4, cD3, cD2, cD1, cD0, cL2E;
};

// l2 = {l_a, l_b} packed f32x2 straight from an LDG.128 half.
__device__ __forceinline__ void pair_elem(u64 l2, u64& accA, u64& accB,
                                          const PkConsts& C) {
    u64 t2 = fma2(C.cTwo, l2, C.cN2T);    // 2*l - 2tau (== 2*fl(l-tau))
    u64 s2 = fma2(C.c2E, t2, C.cTwo);     // 2e*t2 + 2
    float s0, s1; upk2(s0, s1, s2);
    s0 = fmaxf(s0, 0.0f);
    s1 = fmaxf(s1, 0.0f);
    float p0 = fsqrt(s0), p1 = fsqrt(s1);
    u64 p2 = pk2(p0, p1);

    u64 h = fma2(p2, C.cD5, C.cD4);
    h = fma2(p2, h, C.cD3);
    h = fma2(p2, h, C.cD2);
    h = fma2(p2, h, C.cD1);
    h = fma2(p2, h, C.cD0);
    u64 z2 = fma2(p2, h, C.cL2E);         // z = -w*log2e

    accB = fma2(z2, z2, accB);
    float z0, z1; upk2(z0, z1, z2);
    float g0 = fex2(z0), g1 = fex2(z1);   // sigma = exp(-w)
    u64 sg = pk2(g0, g1);
    accA = fma2(t2, sg, accA);
}

__device__ __forceinline__ void do_v2(ulonglong2 v, u64& accA0, u64& accB0,
                                      u64& accA1, u64& accB1, const PkConsts& C) {
    pair_elem(v.x, accA0, accB0, C);
    pair_elem(v.y, accA1, accB1, C);
}

__global__ void __launch_bounds__(NTHREADS, 4)
sl_kernel(const float* __restrict__ in, long long n, float* __restrict__ out) {
    PkConsts C;
    C.cTwo = pk2(2.0f, 2.0f);
    C.cN2T = pk2(NEG_2TAU, NEG_2TAU);
    C.c2E  = pk2(TWO_E, TWO_E);
    C.cD5  = pk2(D5, D5); C.cD4 = pk2(D4, D4); C.cD3 = pk2(D3, D3);
    C.cD2  = pk2(D2, D2); C.cD1 = pk2(D1, D1); C.cD0 = pk2(D0, D0);
    C.cL2E = pk2(LOG2E_F, LOG2E_F);

    u64 accA0 = 0, accB0 = 0, accA1 = 0, accB1 = 0;

    const ulonglong2* __restrict__ in4 = (const ulonglong2*)in;
    int n4 = (int)(n >> 2);                      // 8M 16B-groups
    int tid    = blockIdx.x * NTHREADS + threadIdx.x;
    int stride = NBLOCKS * NTHREADS;             // 262144; n4/stride == 32

    int i = tid;
    // Main path: 8 batched 16B loads per iteration (MLP=8).
    // At N=2^25: exactly 4 iterations, no tail.
    for (; i + 7 * stride < n4; i += 8 * stride) {
        ulonglong2 v0 = in4[i];
        ulonglong2 v1 = in4[i + stride];
        ulonglong2 v2 = in4[i + 2 * stride];
        ulonglong2 v3 = in4[i + 3 * stride];
        ulonglong2 v4 = in4[i + 4 * stride];
        ulonglong2 v5 = in4[i + 5 * stride];
        ulonglong2 v6 = in4[i + 6 * stride];
        ulonglong2 v7 = in4[i + 7 * stride];
        do_v2(v0, accA0, accB0, accA1, accB1, C);
        do_v2(v1, accA0, accB0, accA1, accB1, C);
        do_v2(v2, accA0, accB0, accA1, accB1, C);
        do_v2(v3, accA0, accB0, accA1, accB1, C);
        do_v2(v4, accA0, accB0, accA1, accB1, C);
        do_v2(v5, accA0, accB0, accA1, accB1, C);
        do_v2(v6, accA0, accB0, accA1, accB1, C);
        do_v2(v7, accA0, accB0, accA1, accB1, C);
    }
    for (; i < n4; i += stride) {                // generic tail (not taken at N=2^25)
        ulonglong2 v = in4[i];
        do_v2(v, accA0, accB0, accA1, accB1, C);
    }

    float a0, a1, a2, a3, b0, b1, b2, b3;
    upk2(a0, a1, accA0); upk2(a2, a3, accA1);
    upk2(b0, b1, accB0); upk2(b2, b3, accB1);
    float a = (a0 + a1) + (a2 + a3);
    float b = (b0 + b1) + (b2 + b3);

#pragma unroll
    for (int o = 16; o > 0; o >>= 1) {
        a += __shfl_xor_sync(0xffffffffu, a, o);
        b += __shfl_xor_sync(0xffffffffu, b, o);
    }

    __shared__ float wsA[8], wsB[8];
    int lane = threadIdx.x & 31;
    int wid  = threadIdx.x >> 5;
    if (lane == 0) { wsA[wid] = a; wsB[wid] = b; }
    __syncthreads();

    __shared__ bool isLast;
    if (threadIdx.x == 0) {
        float ba = 0.f, bb = 0.f;
#pragma unroll
        for (int k = 0; k < 8; ++k) { ba += wsA[k]; bb += wsB[k]; }
        __stcg(&g_partA[blockIdx.x], ba);
        __stcg(&g_partB[blockIdx.x], bb);
        __threadfence();
        unsigned int old = atomicInc(&g_cnt, gridDim.x - 1);  // wraps to 0 on last
        isLast = (old == gridDim.x - 1);
    }
    __syncthreads();

    if (isLast) {
        double da = 0.0, db = 0.0;
        for (int k = threadIdx.x; k < NBLOCKS; k += NTHREADS) {
            da += (double)__ldcg(&g_partA[k]);
            db += (double)__ldcg(&g_partB[k]);
        }
#pragma unroll
        for (int o = 16; o > 0; o >>= 1) {
            da += __shfl_xor_sync(0xffffffffu, da, o);
            db += __shfl_xor_sync(0xffffffffu, db, o);
        }
        __shared__ double dsA[8], dsB[8];
        if (lane == 0) { dsA[wid] = da; dsB[wid] = db; }
        __syncthreads();
        if (threadIdx.x == 0) {
            double ta = 0.0, tb = 0.0;
#pragma unroll
            for (int k = 0; k < 8; ++k) { ta += dsA[k]; tb += dsB[k]; }
            const double K = 0.12011325347955035;  // 0.25*ln(2)^2
            out[0] = (float)((0.5 * ta + K * tb) / (double)n);
        }
    }
}

extern "C" void kernel_launch(void* const* d_in, const int* in_sizes, int n_in,
                              void* d_out, int out_size) {
    const float* l_i = (const float*)d_in[0];
    long long n = (long long)in_sizes[0];
    float* out = (float*)d_out;
    sl_kernel<<<NBLOCKS, NTHREADS>>>(l_i, n, out);
}

// round 15
// speedup vs baseline: 1.0087x; 1.0087x over previous
#include <cuda_runtime.h>

// SuperLoss mean, single-kernel. loss_i = (l-tau)*sigma + 0.25*ln(sigma)^2,
// sigma = exp(-W0(y)), y = max(-1/e, 2*(l-tau)).
//
// w = -1 + p*g(p), p = sqrt(max(2e*t2 + 2, 0)), t2 = 2*(l-tau).
// Deg-5 poly for g pre-scaled by -log2e: z = -w*log2e feeds ex2.approx;
// 0.25*w^2 = K*z^2 in the final combine. Core math frozen since R9.
//
// R14: block-contiguous tiling (128KiB/block) so the 4 MLP loads per
// iteration are consecutive 16B groups addressed by constant immediate
// offsets (no per-load IMAD, 2KiB contiguous per warp-quad); scalar accA
// (drops the sigma repack); guard-free exact main loop.

#define NEG_2TAU  (-11.5981853089210513f)
#define TWO_E     ( 5.43656365691809047f)
#define LOG2E_F   ( 1.44269504088896341f)

#define D5 ( 4.8619e-4f)
#define D4 (-7.70688e-3f)
#define D3 ( 4.942817e-2f)
#define D2 (-1.7750919e-1f)
#define D1 ( 4.7082352e-1f)
#define D0 (-1.44269504f)

#define NBLOCKS  1024
#define NTHREADS 256
#define GPT      32          // 16B groups per thread
#define GPB      (NTHREADS * GPT)   // 8192 groups per block

typedef unsigned long long u64;

__device__ float g_partA[NBLOCKS];
__device__ float g_partB[NBLOCKS];
__device__ unsigned int g_cnt = 0;   // self-resets via atomicInc wraparound

__device__ __forceinline__ u64 pk2(float lo, float hi) {
    u64 r; asm("mov.b64 %0, {%1, %2};" : "=l"(r) : "f"(lo), "f"(hi)); return r;
}
__device__ __forceinline__ void upk2(float& lo, float& hi, u64 v) {
    asm("mov.b64 {%0, %1}, %2;" : "=f"(lo), "=f"(hi) : "l"(v));
}
__device__ __forceinline__ u64 fma2(u64 a, u64 b, u64 c) {
    u64 d; asm("fma.rn.f32x2 %0, %1, %2, %3;" : "=l"(d) : "l"(a), "l"(b), "l"(c)); return d;
}
__device__ __forceinline__ float fsqrt(float x) {
    float r; asm("sqrt.approx.f32 %0, %1;" : "=f"(r) : "f"(x)); return r;
}
__device__ __forceinline__ float fex2(float x) {
    float r; asm("ex2.approx.f32 %0, %1;" : "=f"(r) : "f"(x)); return r;
}

struct PkConsts {
    u64 cTwo, cN2T, c2E, cD5, cD4, cD3, cD2, cD1, cD0, cL2E;
};

// l2 = {l_a, l_b} packed f32x2 (one 64-bit half of an LDG.128).
// accA kept as two scalars (a_lo, a_hi): kills the sigma repack.
__device__ __forceinline__ void pair_elem(u64 l2, float& a_lo, float& a_hi,
                                          u64& accB, const PkConsts& C) {
    u64 t2 = fma2(C.cTwo, l2, C.cN2T);    // 2*l - 2tau (== 2*fl(l-tau))
    u64 s2 = fma2(C.c2E, t2, C.cTwo);     // 2e*t2 + 2
    float s0, s1; upk2(s0, s1, s2);
    s0 = fmaxf(s0, 0.0f);
    s1 = fmaxf(s1, 0.0f);
    float p0 = fsqrt(s0), p1 = fsqrt(s1);
    u64 p2 = pk2(p0, p1);

    u64 h = fma2(p2, C.cD5, C.cD4);
    h = fma2(p2, h, C.cD3);
    h = fma2(p2, h, C.cD2);
    h = fma2(p2, h, C.cD1);
    h = fma2(p2, h, C.cD0);
    u64 z2 = fma2(p2, h, C.cL2E);         // z = -w*log2e

    accB = fma2(z2, z2, accB);
    float z0, z1; upk2(z0, z1, z2);
    float g0 = fex2(z0), g1 = fex2(z1);   // sigma = exp(-w)
    float t0, t1; upk2(t0, t1, t2);
    a_lo = fmaf(t0, g0, a_lo);
    a_hi = fmaf(t1, g1, a_hi);
}

__device__ __forceinline__ void do_v2(ulonglong2 v, float& a0, float& a1,
                                      float& a2, float& a3,
                                      u64& accB0, u64& accB1, const PkConsts& C) {
    pair_elem(v.x, a0, a1, accB0, C);
    pair_elem(v.y, a2, a3, accB1, C);
}

__global__ void __launch_bounds__(NTHREADS, 4)
sl_kernel(const float* __restrict__ in, long long n, float* __restrict__ out) {
    PkConsts C;
    C.cTwo = pk2(2.0f, 2.0f);
    C.cN2T = pk2(NEG_2TAU, NEG_2TAU);
    C.c2E  = pk2(TWO_E, TWO_E);
    C.cD5  = pk2(D5, D5); C.cD4 = pk2(D4, D4); C.cD3 = pk2(D3, D3);
    C.cD2  = pk2(D2, D2); C.cD1 = pk2(D1, D1); C.cD0 = pk2(D0, D0);
    C.cL2E = pk2(LOG2E_F, LOG2E_F);

    float a0 = 0.f, a1 = 0.f, a2 = 0.f, a3 = 0.f;
    u64 accB0 = 0, accB1 = 0;

    const ulonglong2* __restrict__ in4 = (const ulonglong2*)in;
    int n4 = (int)(n >> 2);                      // 16B groups

    if (n4 == NBLOCKS * GPB) {
        // Fast path: block-contiguous tile, exact coverage, no guards.
        // Thread t of block b: groups b*GPB + k*(NTHREADS*4) + t*4 + {0..3},
        // k = 0..7. Warp reads 2KiB contiguous per iteration-quad.
        const ulonglong2* base = in4 + (size_t)blockIdx.x * GPB + threadIdx.x * 4;
#pragma unroll 1
        for (int k = 0; k < GPT / 4; ++k) {
            const ulonglong2* bk = base + k * (NTHREADS * 4);
            ulonglong2 v0 = __ldcs(bk + 0);
            ulonglong2 v1 = __ldcs(bk + 1);
            ulonglong2 v2 = __ldcs(bk + 2);
            ulonglong2 v3 = __ldcs(bk + 3);
            do_v2(v0, a0, a1, a2, a3, accB0, accB1, C);
            do_v2(v1, a0, a1, a2, a3, accB0, accB1, C);
            do_v2(v2, a0, a1, a2, a3, accB0, accB1, C);
            do_v2(v3, a0, a1, a2, a3, accB0, accB1, C);
        }
    } else {
        // Generic fallback: grid-stride.
        int tid    = blockIdx.x * NTHREADS + threadIdx.x;
        int stride = NBLOCKS * NTHREADS;
        for (int i = tid; i < n4; i += stride) {
            ulonglong2 v = __ldcs(&in4[i]);
            do_v2(v, a0, a1, a2, a3, accB0, accB1, C);
        }
    }

    float b0, b1, b2, b3;
    upk2(b0, b1, accB0); upk2(b2, b3, accB1);
    float a = (a0 + a1) + (a2 + a3);
    float b = (b0 + b1) + (b2 + b3);

#pragma unroll
    for (int o = 16; o > 0; o >>= 1) {
        a += __shfl_xor_sync(0xffffffffu, a, o);
        b += __shfl_xor_sync(0xffffffffu, b, o);
    }

    __shared__ float wsA[8], wsB[8];
    int lane = threadIdx.x & 31;
    int wid  = threadIdx.x >> 5;
    if (lane == 0) { wsA[wid] = a; wsB[wid] = b; }
    __syncthreads();

    __shared__ bool isLast;
    if (threadIdx.x == 0) {
        float ba = 0.f, bb = 0.f;
#pragma unroll
        for (int k = 0; k < 8; ++k) { ba += wsA[k]; bb += wsB[k]; }
        __stcg(&g_partA[blockIdx.x], ba);
        __stcg(&g_partB[blockIdx.x], bb);
        __threadfence();
        unsigned int old = atomicInc(&g_cnt, gridDim.x - 1);  // wraps to 0 on last
        isLast = (old == gridDim.x - 1);
    }
    __syncthreads();

    if (isLast) {
        double da = 0.0, db = 0.0;
        for (int k = threadIdx.x; k < NBLOCKS; k += NTHREADS) {
            da += (double)__ldcg(&g_partA[k]);
            db += (double)__ldcg(&g_partB[k]);
        }
#pragma unroll
        for (int o = 16; o > 0; o >>= 1) {
            da += __shfl_xor_sync(0xffffffffu, da, o);
            db += __shfl_xor_sync(0xffffffffu, db, o);
        }
        __shared__ double dsA[8], dsB[8];
        if (lane == 0) { dsA[wid] = da; dsB[wid] = db; }
        __syncthreads();
        if (threadIdx.x == 0) {
            double ta = 0.0, tb = 0.0;
#pragma unroll
            for (int k = 0; k < 8; ++k) { ta += dsA[k]; tb += dsB[k]; }
            const double K = 0.12011325347955035;  // 0.25*ln(2)^2
            out[0] = (float)((0.5 * ta + K * tb) / (double)n);
        }
    }
}

extern "C" void kernel_launch(void* const* d_in, const int* in_sizes, int n_in,
                              void* d_out, int out_size) {
    const float* l_i = (const float*)d_in[0];
    long long n = (long long)in_sizes[0];
    float* out = (float*)d_out;
    sl_kernel<<<NBLOCKS, NTHREADS>>>(l_i, n, out);
}

// round 16
// speedup vs baseline: 1.0325x; 1.0236x over previous
#include <cuda_runtime.h>

// SuperLoss mean, single-kernel. loss_i = (l-tau)*sigma + 0.25*ln(sigma)^2,
// sigma = exp(-W0(y)), y = max(-1/e, 2*(l-tau)).
//
// w = -1 + p*g(p), p = sqrt(max(2e*t2 + 2, 0)), t2 = 2*(l-tau).
// Deg-5 poly for g pre-scaled by -log2e: z = -w*log2e feeds ex2.approx;
// 0.25*w^2 = K*z^2 in the final combine. Core math frozen since R9.
//
// R15: explicit double-buffered software pipeline. Block owns a contiguous
// 128KiB tile; per thread 8 batches of 4 coalesced LDG.128, ALL with
// compile-time immediate offsets off one base pointer. Ping-pong A/B buffers
// keep >=1 batch in flight behind every compute phase, so per-iteration
// head-of-loop DRAM latency (the hypothesized residual stall) is hidden.

#define NEG_2TAU  (-11.5981853089210513f)
#define TWO_E     ( 5.43656365691809047f)
#define LOG2E_F   ( 1.44269504088896341f)

#define D5 ( 4.8619e-4f)
#define D4 (-7.70688e-3f)
#define D3 ( 4.942817e-2f)
#define D2 (-1.7750919e-1f)
#define D1 ( 4.7082352e-1f)
#define D0 (-1.44269504f)

#define NBLOCKS  1024
#define NTHREADS 256
#define GPT      32                 // 16B groups per thread
#define GPB      (NTHREADS * GPT)   // 8192 groups per block (128KiB)

typedef unsigned long long u64;

__device__ float g_partA[NBLOCKS];
__device__ float g_partB[NBLOCKS];
__device__ unsigned int g_cnt = 0;   // self-resets via atomicInc wraparound

__device__ __forceinline__ u64 pk2(float lo, float hi) {
    u64 r; asm("mov.b64 %0, {%1, %2};" : "=l"(r) : "f"(lo), "f"(hi)); return r;
}
__device__ __forceinline__ void upk2(float& lo, float& hi, u64 v) {
    asm("mov.b64 {%0, %1}, %2;" : "=f"(lo), "=f"(hi) : "l"(v));
}
__device__ __forceinline__ u64 fma2(u64 a, u64 b, u64 c) {
    u64 d; asm("fma.rn.f32x2 %0, %1, %2, %3;" : "=l"(d) : "l"(a), "l"(b), "l"(c)); return d;
}
__device__ __forceinline__ float fsqrt(float x) {
    float r; asm("sqrt.approx.f32 %0, %1;" : "=f"(r) : "f"(x)); return r;
}
__device__ __forceinline__ float fex2(float x) {
    float r; asm("ex2.approx.f32 %0, %1;" : "=f"(r) : "f"(x)); return r;
}

struct PkConsts {
    u64 cTwo, cN2T, c2E, cD5, cD4, cD3, cD2, cD1, cD0, cL2E;
};

// l2 = {l_a, l_b} packed f32x2 (one 64-bit half of an LDG.128).
__device__ __forceinline__ void pair_elem(u64 l2, float& a_lo, float& a_hi,
                                          u64& accB, const PkConsts& C) {
    u64 t2 = fma2(C.cTwo, l2, C.cN2T);    // 2*l - 2tau (== 2*fl(l-tau))
    u64 s2 = fma2(C.c2E, t2, C.cTwo);     // 2e*t2 + 2
    float s0, s1; upk2(s0, s1, s2);
    s0 = fmaxf(s0, 0.0f);
    s1 = fmaxf(s1, 0.0f);
    float p0 = fsqrt(s0), p1 = fsqrt(s1);
    u64 p2 = pk2(p0, p1);

    u64 h = fma2(p2, C.cD5, C.cD4);
    h = fma2(p2, h, C.cD3);
    h = fma2(p2, h, C.cD2);
    h = fma2(p2, h, C.cD1);
    h = fma2(p2, h, C.cD0);
    u64 z2 = fma2(p2, h, C.cL2E);         // z = -w*log2e

    accB = fma2(z2, z2, accB);
    float z0, z1; upk2(z0, z1, z2);
    float g0 = fex2(z0), g1 = fex2(z1);   // sigma = exp(-w)
    float t0, t1; upk2(t0, t1, t2);
    a_lo = fmaf(t0, g0, a_lo);
    a_hi = fmaf(t1, g1, a_hi);
}

__device__ __forceinline__ void do_v2(ulonglong2 v, float& a0, float& a1,
                                      float& a2, float& a3,
                                      u64& accB0, u64& accB1, const PkConsts& C) {
    pair_elem(v.x, a0, a1, accB0, C);
    pair_elem(v.y, a2, a3, accB1, C);
}

__global__ void __launch_bounds__(NTHREADS, 4)
sl_kernel(const float* __restrict__ in, long long n, float* __restrict__ out) {
    PkConsts C;
    C.cTwo = pk2(2.0f, 2.0f);
    C.cN2T = pk2(NEG_2TAU, NEG_2TAU);
    C.c2E  = pk2(TWO_E, TWO_E);
    C.cD5  = pk2(D5, D5); C.cD4 = pk2(D4, D4); C.cD3 = pk2(D3, D3);
    C.cD2  = pk2(D2, D2); C.cD1 = pk2(D1, D1); C.cD0 = pk2(D0, D0);
    C.cL2E = pk2(LOG2E_F, LOG2E_F);

    float a0 = 0.f, a1 = 0.f, a2 = 0.f, a3 = 0.f;
    u64 accB0 = 0, accB1 = 0;

    const ulonglong2* __restrict__ in4 = (const ulonglong2*)in;
    int n4 = (int)(n >> 2);                      // 16B groups

    if (n4 == NBLOCKS * GPB) {
        // Fast path: contiguous 128KiB block tile. Batch k (k=0..7) for
        // thread t = groups {t + j*256 + k*1024, j=0..3}: coalesced
        // (stride 16B across lanes) and immediate-offset (j*4KiB + k*16KiB).
        const ulonglong2* base = in4 + (size_t)blockIdx.x * GPB + threadIdx.x;

#define LD(Bf, k)                                              \
        do {                                                   \
            Bf##0 = __ldcs(base + (k) * 1024 + 0);             \
            Bf##1 = __ldcs(base + (k) * 1024 + 256);           \
            Bf##2 = __ldcs(base + (k) * 1024 + 512);           \
            Bf##3 = __ldcs(base + (k) * 1024 + 768);           \
        } while (0)
#define CP(Bf)                                                 \
        do {                                                   \
            do_v2(Bf##0, a0, a1, a2, a3, accB0, accB1, C);     \
            do_v2(Bf##1, a0, a1, a2, a3, accB0, accB1, C);     \
            do_v2(Bf##2, a0, a1, a2, a3, accB0, accB1, C);     \
            do_v2(Bf##3, a0, a1, a2, a3, accB0, accB1, C);     \
        } while (0)

        ulonglong2 A0, A1, A2, A3, B0, B1, B2, B3;
        LD(A, 0);
        LD(B, 1);
        CP(A); LD(A, 2);
        CP(B); LD(B, 3);
        CP(A); LD(A, 4);
        CP(B); LD(B, 5);
        CP(A); LD(A, 6);
        CP(B); LD(B, 7);
        CP(A);
        CP(B);
#undef LD
#undef CP
    } else {
        // Generic fallback: grid-stride.
        int tid    = blockIdx.x * NTHREADS + threadIdx.x;
        int stride = NBLOCKS * NTHREADS;
        for (int i = tid; i < n4; i += stride) {
            ulonglong2 v = __ldcs(&in4[i]);
            do_v2(v, a0, a1, a2, a3, accB0, accB1, C);
        }
    }

    float b0, b1, b2, b3;
    upk2(b0, b1, accB0); upk2(b2, b3, accB1);
    float a = (a0 + a1) + (a2 + a3);
    float b = (b0 + b1) + (b2 + b3);

#pragma unroll
    for (int o = 16; o > 0; o >>= 1) {
        a += __shfl_xor_sync(0xffffffffu, a, o);
        b += __shfl_xor_sync(0xffffffffu, b, o);
    }

    __shared__ float wsA[8], wsB[8];
    int lane = threadIdx.x & 31;
    int wid  = threadIdx.x >> 5;
    if (lane == 0) { wsA[wid] = a; wsB[wid] = b; }
    __syncthreads();

    __shared__ bool isLast;
    if (threadIdx.x == 0) {
        float ba = 0.f, bb = 0.f;
#pragma unroll
        for (int k = 0; k < 8; ++k) { ba += wsA[k]; bb += wsB[k]; }
        __stcg(&g_partA[blockIdx.x], ba);
        __stcg(&g_partB[blockIdx.x], bb);
        __threadfence();
        unsigned int old = atomicInc(&g_cnt, gridDim.x - 1);  // wraps to 0 on last
        isLast = (old == gridDim.x - 1);
    }
    __syncthreads();

    if (isLast) {
        double da = 0.0, db = 0.0;
        for (int k = threadIdx.x; k < NBLOCKS; k += NTHREADS) {
            da += (double)__ldcg(&g_partA[k]);
            db += (double)__ldcg(&g_partB[k]);
        }
#pragma unroll
        for (int o = 16; o > 0; o >>= 1) {
            da += __shfl_xor_sync(0xffffffffu, da, o);
            db += __shfl_xor_sync(0xffffffffu, db, o);
        }
        __shared__ double dsA[8], dsB[8];
        if (lane == 0) { dsA[wid] = da; dsB[wid] = db; }
        __syncthreads();
        if (threadIdx.x == 0) {
            double ta = 0.0, tb = 0.0;
#pragma unroll
            for (int k = 0; k < 8; ++k) { ta += dsA[k]; tb += dsB[k]; }
            const double K = 0.12011325347955035;  // 0.25*ln(2)^2
            out[0] = (float)((0.5 * ta + K * tb) / (double)n);
        }
    }
}

extern "C" void kernel_launch(void* const* d_in, const int* in_sizes, int n_in,
                              void* d_out, int out_size) {
    const float* l_i = (const float*)d_in[0];
    long long n = (long long)in_sizes[0];
    float* out = (float*)d_out;
    sl_kernel<<<NBLOCKS, NTHREADS>>>(l_i, n, out);
}